// round 1
// baseline (speedup 1.0000x reference)
#include <cuda_runtime.h>
#include <cstdint>
#include <math.h>

#define HID    1024
#define BATCH  4
#define SEQ    4096
#define NHEAD  16
#define HDIM   64
#define MTOT   (BATCH * SEQ)   // 16384 tokens

// ---------------------------------------------------------------------------
// Scratch (device globals: allocation-free per harness rules)
// ---------------------------------------------------------------------------
__device__ float g_q[MTOT * HID];
__device__ float g_k[MTOT * HID];
__device__ float g_v[MTOT * HID];
__device__ float g_attn[MTOT * HID];

// ---------------------------------------------------------------------------
// Packed f32x2 helpers (sm_103a packed fp32 FMA — PTX only, 2x FFMA rate)
// ---------------------------------------------------------------------------
__device__ __forceinline__ unsigned long long pack2(float lo, float hi) {
    unsigned long long r;
    asm("mov.b64 %0, {%1, %2};" : "=l"(r) : "f"(lo), "f"(hi));
    return r;
}
__device__ __forceinline__ void unpack2(unsigned long long v, float& lo, float& hi) {
    asm("mov.b64 {%0, %1}, %2;" : "=f"(lo), "=f"(hi) : "l"(v));
}
__device__ __forceinline__ unsigned long long fma2(unsigned long long a,
                                                   unsigned long long b,
                                                   unsigned long long c) {
    unsigned long long d;
    asm("fma.rn.f32x2 %0, %1, %2, %3;" : "=l"(d) : "l"(a), "l"(b), "l"(c));
    return d;
}

// ---------------------------------------------------------------------------
// GEMM: C[M,N] = A[M,K] @ B[K,N] + bias[N]
// Block tile 128x128, K-tile 16, 256 threads, 8x8 microtile per thread.
// grid.z selects among up to 3 (B, bias, C) triples so the QKV projections
// go out in a single launch.
// ---------------------------------------------------------------------------
#define TM 128
#define TN 128
#define TK 16
#define AS_PAD 132   // padded row length for the transposed A tile

__global__ __launch_bounds__(256)
void gemm_bias_kernel(const float* __restrict__ A,
                      const float* __restrict__ W0, const float* __restrict__ W1,
                      const float* __restrict__ W2,
                      const float* __restrict__ b0, const float* __restrict__ b1,
                      const float* __restrict__ b2,
                      float* __restrict__ C0, float* __restrict__ C1,
                      float* __restrict__ C2,
                      int M, int K, int N)
{
    const int z = blockIdx.z;
    const float* __restrict__ Bm   = (z == 0) ? W0 : (z == 1) ? W1 : W2;
    const float* __restrict__ bias = (z == 0) ? b0 : (z == 1) ? b1 : b2;
    float*       __restrict__ C    = (z == 0) ? C0 : (z == 1) ? C1 : C2;

    __shared__ float As[TK][AS_PAD];  // A tile transposed: As[k][m]
    __shared__ float Bs[TK][TN];      // B tile: Bs[k][n]

    const int t  = threadIdx.x;
    const int tn = t & 15;   // 0..15
    const int tm = t >> 4;   // 0..15

    const int m0 = blockIdx.y * TM;
    const int n0 = blockIdx.x * TN;

    // 8 rows x 4 column-pairs of packed-f32x2 accumulators (= 8x8 fp32)
    unsigned long long acc[8][4];
#pragma unroll
    for (int i = 0; i < 8; i++)
#pragma unroll
        for (int j = 0; j < 4; j++) acc[i][j] = 0ull;

    for (int k0 = 0; k0 < K; k0 += TK) {
        // Load A tile (128 rows x 16 k) as float4, store transposed.
#pragma unroll
        for (int i = 0; i < 2; i++) {
            int s   = t + i * 256;          // 512 float4 slots
            int row = s >> 2;
            int kk4 = (s & 3) << 2;
            float4 va = *reinterpret_cast<const float4*>(
                &A[(size_t)(m0 + row) * K + k0 + kk4]);
            As[kk4 + 0][row] = va.x;
            As[kk4 + 1][row] = va.y;
            As[kk4 + 2][row] = va.z;
            As[kk4 + 3][row] = va.w;
        }
        // Load B tile (16 k x 128 n) as float4 (coalesced, conflict-free).
#pragma unroll
        for (int i = 0; i < 2; i++) {
            int s  = t + i * 256;           // 512 float4 slots
            int kk = s >> 5;
            int c4 = (s & 31) << 2;
            *reinterpret_cast<float4*>(&Bs[kk][c4]) =
                *reinterpret_cast<const float4*>(
                    &Bm[(size_t)(k0 + kk) * N + n0 + c4]);
        }
        __syncthreads();

#pragma unroll
        for (int kk = 0; kk < TK; kk++) {
            float a[8];
            float4 a0 = *reinterpret_cast<const float4*>(&As[kk][tm * 4]);
            float4 a1 = *reinterpret_cast<const float4*>(&As[kk][64 + tm * 4]);
            a[0] = a0.x; a[1] = a0.y; a[2] = a0.z; a[3] = a0.w;
            a[4] = a1.x; a[5] = a1.y; a[6] = a1.z; a[7] = a1.w;

            float4 q0 = *reinterpret_cast<const float4*>(&Bs[kk][tn * 4]);
            float4 q1 = *reinterpret_cast<const float4*>(&Bs[kk][64 + tn * 4]);
            unsigned long long b2r[4];
            b2r[0] = pack2(q0.x, q0.y);
            b2r[1] = pack2(q0.z, q0.w);
            b2r[2] = pack2(q1.x, q1.y);
            b2r[3] = pack2(q1.z, q1.w);

#pragma unroll
            for (int r = 0; r < 8; r++) {
                unsigned long long ar = pack2(a[r], a[r]);
#pragma unroll
                for (int c = 0; c < 4; c++)
                    acc[r][c] = fma2(ar, b2r[c], acc[r][c]);
            }
        }
        __syncthreads();
    }

    // Epilogue: add bias, write two float4s per row (coalesced across tn).
    float bv[8];
#pragma unroll
    for (int j = 0; j < 4; j++) {
        bv[j]     = bias[n0 + tn * 4 + j];
        bv[4 + j] = bias[n0 + 64 + tn * 4 + j];
    }
#pragma unroll
    for (int r = 0; r < 8; r++) {
        int row = m0 + ((r < 4) ? (tm * 4 + r) : (64 + tm * 4 + (r - 4)));
        float o[8];
#pragma unroll
        for (int c = 0; c < 4; c++) {
            float lo, hi;
            unpack2(acc[r][c], lo, hi);
            o[c * 2] = lo; o[c * 2 + 1] = hi;
        }
        float4 w0 = make_float4(o[0] + bv[0], o[1] + bv[1], o[2] + bv[2], o[3] + bv[3]);
        float4 w1 = make_float4(o[4] + bv[4], o[5] + bv[5], o[6] + bv[6], o[7] + bv[7]);
        *reinterpret_cast<float4*>(&C[(size_t)row * N + n0 + tn * 4])      = w0;
        *reinterpret_cast<float4*>(&C[(size_t)row * N + n0 + 64 + tn * 4]) = w1;
    }
}

// ---------------------------------------------------------------------------
// Per-token head-to-head attention.
// One block per token. scores[h,e] = q_h . k_e / sqrt(64); softmax over e;
// out[h,:] = sum_e probs[h,e] * v_e.
// k stored transposed in smem (sk[d][e]) so the score dot-product is
// conflict-free across lanes.
// ---------------------------------------------------------------------------
__global__ __launch_bounds__(256)
void attention_kernel(const float* __restrict__ q,
                      const float* __restrict__ k,
                      const float* __restrict__ v,
                      float* __restrict__ attn)
{
    __shared__ float sq[HID];            // [h*64 + d]
    __shared__ float skT[HDIM * NHEAD];  // [d*16 + e]  (transposed K)
    __shared__ float sv[HID];            // [e*64 + d]
    __shared__ float sprob[NHEAD * NHEAD];

    const int    t    = threadIdx.x;
    const size_t base = (size_t)blockIdx.x * HID;

#pragma unroll
    for (int i = t; i < HID; i += 256) {
        sq[i] = q[base + i];
        sv[i] = v[base + i];
        skT[(i & 63) * NHEAD + (i >> 6)] = k[base + i];
    }
    __syncthreads();

    // 256 threads = one (h,e) score each
    {
        int h = t >> 4, e = t & 15;
        float s = 0.f;
#pragma unroll
        for (int d = 0; d < HDIM; d++)
            s += sq[h * HDIM + d] * skT[d * NHEAD + e];
        sprob[t] = s * 0.125f;   // 1/sqrt(64)
    }
    __syncthreads();

    // Softmax per head row (threads 0..15)
    if (t < NHEAD) {
        int h = t;
        float mx = -1e30f;
#pragma unroll
        for (int e = 0; e < NHEAD; e++) mx = fmaxf(mx, sprob[h * NHEAD + e]);
        float ex[NHEAD];
        float sum = 0.f;
#pragma unroll
        for (int e = 0; e < NHEAD; e++) {
            ex[e] = expf(sprob[h * NHEAD + e] - mx);
            sum  += ex[e];
        }
        float inv = 1.f / sum;
#pragma unroll
        for (int e = 0; e < NHEAD; e++) sprob[h * NHEAD + e] = ex[e] * inv;
    }
    __syncthreads();

    // out: 1024 values, 4 per thread, coalesced (c = t + j*256)
#pragma unroll
    for (int j = 0; j < 4; j++) {
        int   c = t + j * 256;
        int   h = c >> 6, d = c & 63;
        float o = 0.f;
#pragma unroll
        for (int e = 0; e < NHEAD; e++)
            o += sprob[h * NHEAD + e] * sv[e * HDIM + d];
        attn[base + c] = o;
    }
}

// ---------------------------------------------------------------------------
// Launch
// ---------------------------------------------------------------------------
extern "C" void kernel_launch(void* const* d_in, const int* in_sizes, int n_in,
                              void* d_out, int out_size)
{
    const float* x  = (const float*)d_in[0];
    const float* Wq = (const float*)d_in[1];
    const float* bq = (const float*)d_in[2];
    const float* Wk = (const float*)d_in[3];
    const float* bk = (const float*)d_in[4];
    const float* Wv = (const float*)d_in[5];
    const float* bv = (const float*)d_in[6];
    const float* Wo = (const float*)d_in[7];
    const float* bo = (const float*)d_in[8];
    float* out = (float*)d_out;

    float *qp, *kp, *vp, *ap;
    cudaGetSymbolAddress((void**)&qp, g_q);
    cudaGetSymbolAddress((void**)&kp, g_k);
    cudaGetSymbolAddress((void**)&vp, g_v);
    cudaGetSymbolAddress((void**)&ap, g_attn);

    // 1) QKV projections in one launch (grid.z selects W/b/output)
    dim3 gridQKV(HID / TN, MTOT / TM, 3);
    gemm_bias_kernel<<<gridQKV, 256>>>(x, Wq, Wk, Wv, bq, bk, bv,
                                       qp, kp, vp, MTOT, HID, HID);

    // 2) Per-token attention
    attention_kernel<<<MTOT, 256>>>(qp, kp, vp, ap);

    // 3) Output projection
    dim3 gridO(HID / TN, MTOT / TM, 1);
    gemm_bias_kernel<<<gridO, 256>>>(ap, Wo, Wo, Wo, bo, bo, bo,
                                     out, out, out, MTOT, HID, HID);
}

// round 3
// speedup vs baseline: 2.5096x; 2.5096x over previous
#include <cuda_runtime.h>
#include <cstdint>
#include <math.h>

#define HID    1024
#define MTOT   16384      // 4 * 4096 tokens
#define NHEAD  16
#define HDIM   64

// ---------------------------------------------------------------------------
// Scratch (device globals; allocation-free per harness rules)
// ---------------------------------------------------------------------------
__device__ float g_xa[MTOT * HID];        // x converted to tf32 (rna)
__device__ float g_wt[4][HID * HID];      // Wq,Wk,Wv,Wo transposed + tf32(rna)
__device__ float g_q[MTOT * HID];
__device__ float g_k[MTOT * HID];
__device__ float g_v[MTOT * HID];
__device__ float g_attn[MTOT * HID];      // attention out, tf32(rna)

// ---------------------------------------------------------------------------
// Helpers (portable PTX only: no 'a'-gated instructions)
// ---------------------------------------------------------------------------
__device__ __forceinline__ float to_tf32(float x) {
    float r;
    asm("cvt.rna.tf32.f32 %0, %1;" : "=f"(r) : "f"(x));
    return r;
}
__device__ __forceinline__ void cp_async16(uint32_t dst, const void* src) {
    asm volatile("cp.async.cg.shared.global [%0], [%1], 16;" :: "r"(dst), "l"(src));
}
#define CP_COMMIT()   asm volatile("cp.async.commit_group;" ::: "memory")
#define CP_WAIT(n)    asm volatile("cp.async.wait_group %0;" :: "n"(n) : "memory")

__device__ __forceinline__ uint32_t smem_u32(const void* p) {
    uint32_t a;
    asm("{ .reg .u64 t; cvta.to.shared.u64 t, %1; cvt.u32.u64 %0, t; }"
        : "=r"(a) : "l"(p));
    return a;
}

__device__ __forceinline__ void mma_tf32(float c[4],
                                         uint32_t a0, uint32_t a1,
                                         uint32_t a2, uint32_t a3,
                                         uint32_t b0, uint32_t b1) {
    asm volatile(
        "mma.sync.aligned.m16n8k8.row.col.f32.tf32.tf32.f32 "
        "{%0,%1,%2,%3}, {%4,%5,%6,%7}, {%8,%9}, {%0,%1,%2,%3};"
        : "+f"(c[0]), "+f"(c[1]), "+f"(c[2]), "+f"(c[3])
        : "r"(a0), "r"(a1), "r"(a2), "r"(a3), "r"(b0), "r"(b1));
}

// ---------------------------------------------------------------------------
// Staging: tf32 convert + weight transpose
// ---------------------------------------------------------------------------
__global__ __launch_bounds__(256)
void convert_x_kernel(const float* __restrict__ x, float* __restrict__ xa) {
    int i = blockIdx.x * 256 + threadIdx.x;  // float4 index
    float4 v = reinterpret_cast<const float4*>(x)[i];
    v.x = to_tf32(v.x); v.y = to_tf32(v.y); v.z = to_tf32(v.z); v.w = to_tf32(v.w);
    reinterpret_cast<float4*>(xa)[i] = v;
}

__global__ __launch_bounds__(256)
void transpose_w_kernel(const float* __restrict__ W0, const float* __restrict__ W1,
                        const float* __restrict__ W2, const float* __restrict__ W3,
                        float* __restrict__ T) {
    __shared__ float tile[32][33];
    const float* __restrict__ W =
        (blockIdx.z == 0) ? W0 : (blockIdx.z == 1) ? W1 : (blockIdx.z == 2) ? W2 : W3;
    float* __restrict__ Tm = T + (size_t)blockIdx.z * HID * HID;

    int tx = threadIdx.x & 31, ty = threadIdx.x >> 5;  // 32x8
    int x0 = blockIdx.x * 32, y0 = blockIdx.y * 32;
#pragma unroll
    for (int j = 0; j < 4; j++)
        tile[ty + j * 8][tx] = W[(size_t)(y0 + ty + j * 8) * HID + x0 + tx];
    __syncthreads();
#pragma unroll
    for (int j = 0; j < 4; j++)
        Tm[(size_t)(x0 + ty + j * 8) * HID + y0 + tx] = to_tf32(tile[tx][ty + j * 8]);
}

// ---------------------------------------------------------------------------
// mma.sync tf32 GEMM: C[M,N] = A[M,K] @ Bt[N,K]^T + bias
// CTA 128x128, BK=16, 3-stage cp.async, 8 warps (2x4), warp tile 64x32.
// Smem tiles stored row-major-by-[m or n] with row stride 20 floats
// (stride%8==4 -> conflict-free fragment gather across 8 lane-groups).
// grid.z picks one of 3 (Bt, bias, C) triples (fused QKV).
// ---------------------------------------------------------------------------
#define BM 128
#define BN 128
#define BK 16
#define RS 20                      // padded row stride (floats)
#define STAGES 3
#define TILE_FLOATS (BM * RS)      // 2560 per operand per stage
#define GSMEM (STAGES * 2 * TILE_FLOATS * 4)   // 61440 bytes

__global__ __launch_bounds__(256, 2)
void gemm_tf32_kernel(const float* __restrict__ A,
                      const float* __restrict__ Bt0, const float* __restrict__ Bt1,
                      const float* __restrict__ Bt2,
                      const float* __restrict__ b0, const float* __restrict__ b1,
                      const float* __restrict__ b2,
                      float* __restrict__ C0, float* __restrict__ C1,
                      float* __restrict__ C2)
{
    extern __shared__ float smf[];   // [As stages | Bs stages]
    const uint32_t sbase = smem_u32(smf);

    const int z = blockIdx.z;
    const float* __restrict__ Bt   = (z == 0) ? Bt0 : (z == 1) ? Bt1 : Bt2;
    const float* __restrict__ bias = (z == 0) ? b0 : (z == 1) ? b1 : b2;
    float*       __restrict__ C    = (z == 0) ? C0 : (z == 1) ? C1 : C2;

    const int tid  = threadIdx.x;
    const int wid  = tid >> 5;
    const int lane = tid & 31;
    const int wm   = wid >> 2;        // 0..1 -> M offset 64*wm
    const int wn   = wid & 3;         // 0..3 -> N offset 32*wn
    const int lg   = lane >> 2;       // 0..7
    const int lr   = lane & 3;        // 0..3

    const int m0 = blockIdx.y * BM;
    const int n0 = blockIdx.x * BN;

    float acc[4][4][4];
#pragma unroll
    for (int i = 0; i < 4; i++)
#pragma unroll
        for (int j = 0; j < 4; j++)
#pragma unroll
            for (int q = 0; q < 4; q++) acc[i][j][q] = 0.f;

    // cp.async geometry: 512 granules (16B) per operand tile; 2 per thread.
    const int grow0 = tid >> 2;            // rows 0..63   (h=0)
    const int gk    = (tid & 3) << 2;      // k offset 0,4,8,12
    const uint32_t dstA0 = sbase + (uint32_t)(grow0 * RS + gk) * 4;
    const uint32_t dstB0 = sbase + (uint32_t)(STAGES * TILE_FLOATS + grow0 * RS + gk) * 4;
    const uint32_t rowstep = (uint32_t)(64 * RS) * 4;   // +64 rows (h=1)

    auto load_stage = [&](int s, int k0) {
        const uint32_t soff = (uint32_t)(s * TILE_FLOATS) * 4;
        const float* Ap = A  + (size_t)(m0 + grow0) * HID + k0 + gk;
        const float* Bp = Bt + (size_t)(n0 + grow0) * HID + k0 + gk;
        cp_async16(dstA0 + soff,           Ap);
        cp_async16(dstA0 + soff + rowstep, Ap + (size_t)64 * HID);
        cp_async16(dstB0 + soff,           Bp);
        cp_async16(dstB0 + soff + rowstep, Bp + (size_t)64 * HID);
        CP_COMMIT();
    };

#pragma unroll
    for (int s = 0; s < STAGES - 1; s++) load_stage(s, s * BK);

    const int KIT = HID / BK;   // 64
#pragma unroll 1
    for (int it = 0; it < KIT; it++) {
        CP_WAIT(STAGES - 2);
        __syncthreads();

        const int s = it % STAGES;
        const float* Ab = smf + s * TILE_FLOATS;
        const float* Bb = smf + STAGES * TILE_FLOATS + s * TILE_FLOATS;

#pragma unroll
        for (int k8 = 0; k8 < 2; k8++) {
            const int k = k8 * 8 + lr;
            uint32_t af[4][4], bf[4][2];
#pragma unroll
            for (int i = 0; i < 4; i++) {
                const int r = wm * 64 + i * 16 + lg;
                af[i][0] = __float_as_uint(Ab[r * RS + k]);
                af[i][1] = __float_as_uint(Ab[(r + 8) * RS + k]);
                af[i][2] = __float_as_uint(Ab[r * RS + k + 4]);
                af[i][3] = __float_as_uint(Ab[(r + 8) * RS + k + 4]);
            }
#pragma unroll
            for (int j = 0; j < 4; j++) {
                const int c = wn * 32 + j * 8 + lg;
                bf[j][0] = __float_as_uint(Bb[c * RS + k]);
                bf[j][1] = __float_as_uint(Bb[c * RS + k + 4]);
            }
#pragma unroll
            for (int i = 0; i < 4; i++)
#pragma unroll
                for (int j = 0; j < 4; j++)
                    mma_tf32(acc[i][j], af[i][0], af[i][1], af[i][2], af[i][3],
                             bf[j][0], bf[j][1]);
        }

        const int jn = it + STAGES - 1;
        if (jn < KIT) load_stage(jn % STAGES, jn * BK);
    }

    // Epilogue: direct float2 stores + bias
#pragma unroll
    for (int i = 0; i < 4; i++) {
        const int row = m0 + wm * 64 + i * 16 + lg;
#pragma unroll
        for (int j = 0; j < 4; j++) {
            const int col = n0 + wn * 32 + j * 8 + lr * 2;
            const float bx = bias[col], by = bias[col + 1];
            float2 v0 = make_float2(acc[i][j][0] + bx, acc[i][j][1] + by);
            float2 v1 = make_float2(acc[i][j][2] + bx, acc[i][j][3] + by);
            *reinterpret_cast<float2*>(&C[(size_t)row * HID + col])       = v0;
            *reinterpret_cast<float2*>(&C[(size_t)(row + 8) * HID + col]) = v1;
        }
    }
}

// ---------------------------------------------------------------------------
// Per-token head-to-head attention (exact fp32; output pre-converted to tf32)
// ---------------------------------------------------------------------------
__global__ __launch_bounds__(256)
void attention_kernel(const float* __restrict__ q,
                      const float* __restrict__ k,
                      const float* __restrict__ v,
                      float* __restrict__ attn)
{
    __shared__ float sq[HID];
    __shared__ float skT[HDIM * NHEAD];
    __shared__ float sv[HID];
    __shared__ float sprob[NHEAD * NHEAD];

    const int    t    = threadIdx.x;
    const size_t base = (size_t)blockIdx.x * HID;

#pragma unroll
    for (int i = t; i < HID; i += 256) {
        sq[i] = q[base + i];
        sv[i] = v[base + i];
        skT[(i & 63) * NHEAD + (i >> 6)] = k[base + i];
    }
    __syncthreads();

    {
        int h = t >> 4, e = t & 15;
        float s = 0.f;
#pragma unroll
        for (int d = 0; d < HDIM; d++)
            s += sq[h * HDIM + d] * skT[d * NHEAD + e];
        sprob[t] = s * 0.125f;
    }
    __syncthreads();

    if (t < NHEAD) {
        int h = t;
        float mx = -1e30f;
#pragma unroll
        for (int e = 0; e < NHEAD; e++) mx = fmaxf(mx, sprob[h * NHEAD + e]);
        float ex[NHEAD];
        float sum = 0.f;
#pragma unroll
        for (int e = 0; e < NHEAD; e++) {
            ex[e] = expf(sprob[h * NHEAD + e] - mx);
            sum  += ex[e];
        }
        float inv = 1.f / sum;
#pragma unroll
        for (int e = 0; e < NHEAD; e++) sprob[h * NHEAD + e] = ex[e] * inv;
    }
    __syncthreads();

#pragma unroll
    for (int j = 0; j < 4; j++) {
        int   c = t + j * 256;
        int   h = c >> 6, d = c & 63;
        float o = 0.f;
#pragma unroll
        for (int e = 0; e < NHEAD; e++)
            o += sprob[h * NHEAD + e] * sv[e * HDIM + d];
        attn[base + c] = to_tf32(o);   // pre-convert for the O projection
    }
}

// ---------------------------------------------------------------------------
// Launch
// ---------------------------------------------------------------------------
extern "C" void kernel_launch(void* const* d_in, const int* in_sizes, int n_in,
                              void* d_out, int out_size)
{
    const float* x  = (const float*)d_in[0];
    const float* Wq = (const float*)d_in[1];
    const float* bq = (const float*)d_in[2];
    const float* Wk = (const float*)d_in[3];
    const float* bk = (const float*)d_in[4];
    const float* Wv = (const float*)d_in[5];
    const float* bv = (const float*)d_in[6];
    const float* Wo = (const float*)d_in[7];
    const float* bo = (const float*)d_in[8];
    float* out = (float*)d_out;

    float *xa, *wt, *qp, *kp, *vp, *ap;
    cudaGetSymbolAddress((void**)&xa, g_xa);
    cudaGetSymbolAddress((void**)&wt, g_wt);
    cudaGetSymbolAddress((void**)&qp, g_q);
    cudaGetSymbolAddress((void**)&kp, g_k);
    cudaGetSymbolAddress((void**)&vp, g_v);
    cudaGetSymbolAddress((void**)&ap, g_attn);

    static bool attr_set = false;
    if (!attr_set) {
        cudaFuncSetAttribute(gemm_tf32_kernel,
                             cudaFuncAttributeMaxDynamicSharedMemorySize, GSMEM);
        attr_set = true;
    }

    // 0) stage: tf32-round x; transpose+round all four weight matrices
    convert_x_kernel<<<(MTOT * HID / 4) / 256, 256>>>(x, xa);
    dim3 gridT(HID / 32, HID / 32, 4);
    transpose_w_kernel<<<gridT, 256>>>(Wq, Wk, Wv, Wo, wt);

    // 1) fused QKV projections
    dim3 gridQKV(HID / BN, MTOT / BM, 3);
    gemm_tf32_kernel<<<gridQKV, 256, GSMEM>>>(
        xa, wt + 0 * (size_t)HID * HID, wt + 1 * (size_t)HID * HID,
        wt + 2 * (size_t)HID * HID, bq, bk, bv, qp, kp, vp);

    // 2) per-token attention
    attention_kernel<<<MTOT, 256>>>(qp, kp, vp, ap);

    // 3) output projection
    dim3 gridO(HID / BN, MTOT / BM, 1);
    gemm_tf32_kernel<<<gridO, 256, GSMEM>>>(
        ap, wt + 3 * (size_t)HID * HID, wt + 3 * (size_t)HID * HID,
        wt + 3 * (size_t)HID * HID, bo, bo, bo, out, out, out);
}

// round 4
// speedup vs baseline: 2.7709x; 1.1041x over previous
#include <cuda_runtime.h>
#include <cstdint>
#include <math.h>

#define HID    1024
#define MTOT   16384      // 4 * 4096 tokens
#define NHEAD  16
#define HDIM   64

// ---------------------------------------------------------------------------
// Scratch (device globals; allocation-free per harness rules)
// ---------------------------------------------------------------------------
__device__ float g_xa[MTOT * HID];        // x converted to tf32 (rna)
__device__ float g_wt[4][HID * HID];      // Wq,Wk,Wv,Wo transposed + tf32(rna)
__device__ float g_q[MTOT * HID];
__device__ float g_k[MTOT * HID];
__device__ float g_v[MTOT * HID];
__device__ float g_attn[MTOT * HID];      // attention out, tf32(rna)

// ---------------------------------------------------------------------------
// Helpers (portable PTX only: no 'a'-gated instructions)
// ---------------------------------------------------------------------------
__device__ __forceinline__ float to_tf32(float x) {
    float r;
    asm("cvt.rna.tf32.f32 %0, %1;" : "=f"(r) : "f"(x));
    return r;
}
__device__ __forceinline__ void cp_async16(uint32_t dst, const void* src) {
    asm volatile("cp.async.cg.shared.global [%0], [%1], 16;" :: "r"(dst), "l"(src));
}
#define CP_COMMIT()   asm volatile("cp.async.commit_group;" ::: "memory")
#define CP_WAIT(n)    asm volatile("cp.async.wait_group %0;" :: "n"(n) : "memory")

__device__ __forceinline__ uint32_t smem_u32(const void* p) {
    uint32_t a;
    asm("{ .reg .u64 t; cvta.to.shared.u64 t, %1; cvt.u32.u64 %0, t; }"
        : "=r"(a) : "l"(p));
    return a;
}

__device__ __forceinline__ void mma_tf32(float c[4],
                                         uint32_t a0, uint32_t a1,
                                         uint32_t a2, uint32_t a3,
                                         uint32_t b0, uint32_t b1) {
    asm volatile(
        "mma.sync.aligned.m16n8k8.row.col.f32.tf32.tf32.f32 "
        "{%0,%1,%2,%3}, {%4,%5,%6,%7}, {%8,%9}, {%0,%1,%2,%3};"
        : "+f"(c[0]), "+f"(c[1]), "+f"(c[2]), "+f"(c[3])
        : "r"(a0), "r"(a1), "r"(a2), "r"(a3), "r"(b0), "r"(b1));
}

__device__ __forceinline__ void ldsm_x4(uint32_t& r0, uint32_t& r1,
                                        uint32_t& r2, uint32_t& r3,
                                        uint32_t addr) {
    asm volatile("ldmatrix.sync.aligned.m8n8.x4.shared.b16 {%0,%1,%2,%3}, [%4];"
                 : "=r"(r0), "=r"(r1), "=r"(r2), "=r"(r3) : "r"(addr));
}

// ---------------------------------------------------------------------------
// Staging: tf32 convert + weight transpose
// ---------------------------------------------------------------------------
__global__ __launch_bounds__(256)
void convert_x_kernel(const float* __restrict__ x, float* __restrict__ xa) {
    int i = blockIdx.x * 256 + threadIdx.x;  // float4 index
    float4 v = reinterpret_cast<const float4*>(x)[i];
    v.x = to_tf32(v.x); v.y = to_tf32(v.y); v.z = to_tf32(v.z); v.w = to_tf32(v.w);
    reinterpret_cast<float4*>(xa)[i] = v;
}

__global__ __launch_bounds__(256)
void transpose_w_kernel(const float* __restrict__ W0, const float* __restrict__ W1,
                        const float* __restrict__ W2, const float* __restrict__ W3,
                        float* __restrict__ T) {
    __shared__ float tile[32][33];
    const float* __restrict__ W =
        (blockIdx.z == 0) ? W0 : (blockIdx.z == 1) ? W1 : (blockIdx.z == 2) ? W2 : W3;
    float* __restrict__ Tm = T + (size_t)blockIdx.z * HID * HID;

    int tx = threadIdx.x & 31, ty = threadIdx.x >> 5;  // 32x8
    int x0 = blockIdx.x * 32, y0 = blockIdx.y * 32;
#pragma unroll
    for (int j = 0; j < 4; j++)
        tile[ty + j * 8][tx] = W[(size_t)(y0 + ty + j * 8) * HID + x0 + tx];
    __syncthreads();
#pragma unroll
    for (int j = 0; j < 4; j++)
        Tm[(size_t)(x0 + ty + j * 8) * HID + y0 + tx] = to_tf32(tile[tx][ty + j * 8]);
}

// ---------------------------------------------------------------------------
// mma.sync tf32 GEMM: C[M,N] = A[M,K] @ Bt[N,K]^T + bias
// CTA 128x128, BK=16, 4-stage cp.async, 8 warps (2x4), warp tile 64x32.
// Fragments gathered with ldmatrix.x4 (8x4-b32 matrix view == tf32 fragment).
// Smem rows stride 20 floats (80B): 16B-aligned rows, LDSM conflict-free.
// grid.z picks one of 3 (Bt, bias, C) triples (fused QKV).
// ---------------------------------------------------------------------------
#define BM 128
#define BN 128
#define BK 16
#define RS 20                      // padded row stride (floats)
#define STAGES 4
#define TILE_FLOATS (BM * RS)      // 2560 per operand per stage
#define GSMEM (STAGES * 2 * TILE_FLOATS * 4)   // 81920 bytes

__global__ __launch_bounds__(256, 2)
void gemm_tf32_kernel(const float* __restrict__ A,
                      const float* __restrict__ Bt0, const float* __restrict__ Bt1,
                      const float* __restrict__ Bt2,
                      const float* __restrict__ b0, const float* __restrict__ b1,
                      const float* __restrict__ b2,
                      float* __restrict__ C0, float* __restrict__ C1,
                      float* __restrict__ C2)
{
    extern __shared__ float smf[];   // [As stages | Bs stages]
    const uint32_t sbase = smem_u32(smf);
    const uint32_t breg  = (uint32_t)(STAGES * TILE_FLOATS) * 4;

    const int z = blockIdx.z;
    const float* __restrict__ Bt   = (z == 0) ? Bt0 : (z == 1) ? Bt1 : Bt2;
    const float* __restrict__ bias = (z == 0) ? b0 : (z == 1) ? b1 : b2;
    float*       __restrict__ C    = (z == 0) ? C0 : (z == 1) ? C1 : C2;

    const int tid  = threadIdx.x;
    const int wid  = tid >> 5;
    const int lane = tid & 31;
    const int wm   = wid >> 2;        // 0..1 -> M offset 64*wm
    const int wn   = wid & 3;         // 0..3 -> N offset 32*wn
    const int lg   = lane >> 2;       // 0..7
    const int lr   = lane & 3;        // 0..3

    const int m0 = blockIdx.y * BM;
    const int n0 = blockIdx.x * BN;

    float acc[4][4][4];
#pragma unroll
    for (int i = 0; i < 4; i++)
#pragma unroll
        for (int j = 0; j < 4; j++)
#pragma unroll
            for (int q = 0; q < 4; q++) acc[i][j][q] = 0.f;

    // ldmatrix lane geometry
    const int sel = lane >> 3;        // 0..3 (matrix select)
    const int lr8 = lane & 7;         // 0..7 (row within matrix)
    // A: m0..m3 = (row+0,k), (row+8,k), (row+0,k+4), (row+8,k+4)
    uint32_t aoff[4];
#pragma unroll
    for (int i = 0; i < 4; i++) {
        int row = wm * 64 + i * 16 + ((sel & 1) ? 8 : 0) + lr8;
        int col = (sel >> 1) * 4;
        aoff[i] = (uint32_t)(row * RS + col) * 4;
    }
    // B: m0..m3 = (n+0,k), (n+0,k+4), (n+8,k), (n+8,k+4) for j-pair base
    uint32_t boff[2];
#pragma unroll
    for (int jp = 0; jp < 2; jp++) {
        int row = wn * 32 + jp * 16 + ((sel >> 1) ? 8 : 0) + lr8;
        int col = (sel & 1) * 4;
        boff[jp] = breg + (uint32_t)(row * RS + col) * 4;
    }

    // cp.async geometry: 512 granules (16B) per operand tile; 2 per thread.
    const int grow0 = tid >> 2;            // rows 0..63   (h=0)
    const int gk    = (tid & 3) << 2;      // k offset 0,4,8,12
    const uint32_t dstA0 = sbase + (uint32_t)(grow0 * RS + gk) * 4;
    const uint32_t dstB0 = sbase + breg + (uint32_t)(grow0 * RS + gk) * 4;
    const uint32_t rowstep = (uint32_t)(64 * RS) * 4;   // +64 rows (h=1)

    auto load_stage = [&](int s, int k0) {
        const uint32_t soff = (uint32_t)(s * TILE_FLOATS) * 4;
        const float* Ap = A  + (size_t)(m0 + grow0) * HID + k0 + gk;
        const float* Bp = Bt + (size_t)(n0 + grow0) * HID + k0 + gk;
        cp_async16(dstA0 + soff,           Ap);
        cp_async16(dstA0 + soff + rowstep, Ap + (size_t)64 * HID);
        cp_async16(dstB0 + soff,           Bp);
        cp_async16(dstB0 + soff + rowstep, Bp + (size_t)64 * HID);
        CP_COMMIT();
    };

#pragma unroll
    for (int s = 0; s < STAGES - 1; s++) load_stage(s, s * BK);

    const int KIT = HID / BK;   // 64
#pragma unroll 1
    for (int it = 0; it < KIT; it++) {
        CP_WAIT(STAGES - 2);
        __syncthreads();

        const int s = it % STAGES;
        const uint32_t soff = sbase + (uint32_t)(s * TILE_FLOATS) * 4;

#pragma unroll
        for (int k8 = 0; k8 < 2; k8++) {
            const uint32_t kb = soff + (uint32_t)(k8 * 8) * 4;
            uint32_t af[4][4], bf[4][2];
#pragma unroll
            for (int i = 0; i < 4; i++)
                ldsm_x4(af[i][0], af[i][1], af[i][2], af[i][3], kb + aoff[i]);
#pragma unroll
            for (int jp = 0; jp < 2; jp++)
                ldsm_x4(bf[jp * 2][0], bf[jp * 2][1],
                        bf[jp * 2 + 1][0], bf[jp * 2 + 1][1], kb + boff[jp]);
#pragma unroll
            for (int i = 0; i < 4; i++)
#pragma unroll
                for (int j = 0; j < 4; j++)
                    mma_tf32(acc[i][j], af[i][0], af[i][1], af[i][2], af[i][3],
                             bf[j][0], bf[j][1]);
        }

        const int jn = it + STAGES - 1;
        if (jn < KIT) load_stage(jn % STAGES, jn * BK);
    }

    // Epilogue: direct float2 stores + bias
#pragma unroll
    for (int i = 0; i < 4; i++) {
        const int row = m0 + wm * 64 + i * 16 + lg;
#pragma unroll
        for (int j = 0; j < 4; j++) {
            const int col = n0 + wn * 32 + j * 8 + lr * 2;
            const float bx = bias[col], by = bias[col + 1];
            float2 v0 = make_float2(acc[i][j][0] + bx, acc[i][j][1] + by);
            float2 v1 = make_float2(acc[i][j][2] + bx, acc[i][j][3] + by);
            *reinterpret_cast<float2*>(&C[(size_t)row * HID + col])       = v0;
            *reinterpret_cast<float2*>(&C[(size_t)(row + 8) * HID + col]) = v1;
        }
    }
}

// ---------------------------------------------------------------------------
// Per-token head-to-head attention, fully float4-vectorized smem.
// One block per token, 256 threads.
// ---------------------------------------------------------------------------
#define ARS 17   // float4 row stride for k/v tiles (conflict-free)

__global__ __launch_bounds__(256)
void attention_kernel(const float* __restrict__ q,
                      const float* __restrict__ k,
                      const float* __restrict__ v,
                      float* __restrict__ attn)
{
    __shared__ float4 sq4[NHEAD * 16];       // [h*16 + d4]
    __shared__ float4 sk4[NHEAD * ARS];      // [e*ARS + d4]
    __shared__ float4 sv4[NHEAD * ARS];      // [e*ARS + d4]
    __shared__ float  sprob[NHEAD * NHEAD];

    const int t = threadIdx.x;
    const int hi = t >> 4;      // head / key-head / output head
    const int lo = t & 15;      // d4 or e
    const size_t base4 = (size_t)blockIdx.x * (HID / 4);

    const float4* q4 = reinterpret_cast<const float4*>(q) + base4;
    const float4* k4 = reinterpret_cast<const float4*>(k) + base4;
    const float4* v4 = reinterpret_cast<const float4*>(v) + base4;

    sq4[t]              = q4[t];
    sk4[hi * ARS + lo]  = k4[t];
    sv4[hi * ARS + lo]  = v4[t];
    __syncthreads();

    // scores: thread (h=hi, e=lo)
    {
        float s = 0.f;
#pragma unroll
        for (int i = 0; i < 16; i++) {
            float4 a = sq4[hi * 16 + i];
            float4 b = sk4[lo * ARS + i];
            s += a.x * b.x + a.y * b.y + a.z * b.z + a.w * b.w;
        }
        sprob[t] = s * 0.125f;   // 1/sqrt(64)
    }
    __syncthreads();

    // softmax per head row
    if (t < NHEAD) {
        float mx = -1e30f;
#pragma unroll
        for (int e = 0; e < NHEAD; e++) mx = fmaxf(mx, sprob[t * NHEAD + e]);
        float ex[NHEAD];
        float sum = 0.f;
#pragma unroll
        for (int e = 0; e < NHEAD; e++) {
            ex[e] = expf(sprob[t * NHEAD + e] - mx);
            sum  += ex[e];
        }
        float inv = 1.f / sum;
#pragma unroll
        for (int e = 0; e < NHEAD; e++) sprob[t * NHEAD + e] = ex[e] * inv;
    }
    __syncthreads();

    // output: thread (h=hi, d4=lo), one float4
    {
        float4 o = make_float4(0.f, 0.f, 0.f, 0.f);
#pragma unroll
        for (int e = 0; e < NHEAD; e++) {
            float  p  = sprob[hi * NHEAD + e];
            float4 vv = sv4[e * ARS + lo];
            o.x += p * vv.x; o.y += p * vv.y; o.z += p * vv.z; o.w += p * vv.w;
        }
        o.x = to_tf32(o.x); o.y = to_tf32(o.y);
        o.z = to_tf32(o.z); o.w = to_tf32(o.w);
        reinterpret_cast<float4*>(attn)[base4 + t] = o;
    }
}

// ---------------------------------------------------------------------------
// Launch
// ---------------------------------------------------------------------------
extern "C" void kernel_launch(void* const* d_in, const int* in_sizes, int n_in,
                              void* d_out, int out_size)
{
    const float* x  = (const float*)d_in[0];
    const float* Wq = (const float*)d_in[1];
    const float* bq = (const float*)d_in[2];
    const float* Wk = (const float*)d_in[3];
    const float* bk = (const float*)d_in[4];
    const float* Wv = (const float*)d_in[5];
    const float* bv = (const float*)d_in[6];
    const float* Wo = (const float*)d_in[7];
    const float* bo = (const float*)d_in[8];
    float* out = (float*)d_out;

    float *xa, *wt, *qp, *kp, *vp, *ap;
    cudaGetSymbolAddress((void**)&xa, g_xa);
    cudaGetSymbolAddress((void**)&wt, g_wt);
    cudaGetSymbolAddress((void**)&qp, g_q);
    cudaGetSymbolAddress((void**)&kp, g_k);
    cudaGetSymbolAddress((void**)&vp, g_v);
    cudaGetSymbolAddress((void**)&ap, g_attn);

    static bool attr_set = false;
    if (!attr_set) {
        cudaFuncSetAttribute(gemm_tf32_kernel,
                             cudaFuncAttributeMaxDynamicSharedMemorySize, GSMEM);
        attr_set = true;
    }

    // 0) stage: tf32-round x; transpose+round all four weight matrices
    convert_x_kernel<<<(MTOT * HID / 4) / 256, 256>>>(x, xa);
    dim3 gridT(HID / 32, HID / 32, 4);
    transpose_w_kernel<<<gridT, 256>>>(Wq, Wk, Wv, Wo, wt);

    // 1) fused QKV projections
    dim3 gridQKV(HID / BN, MTOT / BM, 3);
    gemm_tf32_kernel<<<gridQKV, 256, GSMEM>>>(
        xa, wt + 0 * (size_t)HID * HID, wt + 1 * (size_t)HID * HID,
        wt + 2 * (size_t)HID * HID, bq, bk, bv, qp, kp, vp);

    // 2) per-token attention
    attention_kernel<<<MTOT, 256>>>(qp, kp, vp, ap);

    // 3) output projection
    dim3 gridO(HID / BN, MTOT / BM, 1);
    gemm_tf32_kernel<<<gridO, 256, GSMEM>>>(
        ap, wt + 3 * (size_t)HID * HID, wt + 3 * (size_t)HID * HID,
        wt + 3 * (size_t)HID * HID, bo, bo, bo, out, out, out);
}